// round 7
// baseline (speedup 1.0000x reference)
#include <cuda_runtime.h>

#define N_NODES   100000
#define N_EDGES   1600000
#define NFEAT     48
#define HIDDEN    256
#define TPB       256
#define GRID      592                     // 148 SMs x 4 blocks: co-resident
#define Y_BLOCKS  200                     // phase-1 blocks streaming x.w
#define DEG_BLOCKS (GRID - Y_BLOCKS)      // phase-1 blocks doing deg histogram
#define EPT       8
#define EDGE_ITEMS (N_EDGES / EPT)        // 200000 (each item = 8 edges)
#define NODE4     (N_NODES / 4)           // 25000

// Device scratch (zero-init at load; every call restores g_deg and g_bar to
// all-zeros before returning => identical state each call: deterministic).
__device__ float    g_deg[N_NODES];
__device__ float    g_dinv[N_NODES];
__device__ float    g_y[N_NODES];
__device__ float    g_z[N_NODES];
__device__ float    g_s[N_NODES];
__device__ float    g_cterm;
__device__ unsigned g_bar[4];             // 3 phase barriers + exit counter

// Grid-wide barrier: monotone counter per phase; all GRID blocks co-resident.
__device__ __forceinline__ void grid_sync(int k)
{
    __syncthreads();
    if (threadIdx.x == 0) {
        __threadfence();                          // release prior writes
        atomicAdd(&g_bar[k], 1u);
        while (*(volatile unsigned*)&g_bar[k] < GRID) __nanosleep(64);
        __threadfence();                          // acquire others' writes
    }
    __syncthreads();
}

__global__ void __launch_bounds__(TPB, 4) k_fused(
    const float* __restrict__ x,
    const int*   __restrict__ ei,
    const float* __restrict__ W1,
    const float* __restrict__ bias,
    const float* __restrict__ W2,
    const float* __restrict__ b2,
    float*       __restrict__ out)
{
    const int t = threadIdx.x;
    const int b = blockIdx.x;

    // ===== Phase 1: deg histogram (DEG_BLOCKS) || y = x.(W1@W2) (Y_BLOCKS) =====
    if (b < Y_BLOCKS) {
        __shared__ float sW2[HIDDEN];
        __shared__ float sw[NFEAT];
        __shared__ float sred[TPB];
        sW2[t] = W2[t];
        __syncthreads();

        if (b == 0) {                      // one block publishes cterm
            sred[t] = sW2[t];
            __syncthreads();
            for (int s = TPB / 2; s > 0; s >>= 1) {
                if (t < s) sred[t] += sred[t + s];
                __syncthreads();
            }
            if (t == 0) g_cterm = bias[0] * sred[0] + b2[0];
        }

        // per-block redundant weight fold: w[f] = sum_h W1[f,h]*W2[h]
        int warp = t >> 5, lane = t & 31;
        for (int f = warp; f < NFEAT; f += 8) {
            float p = 0.0f;
            #pragma unroll
            for (int h = lane; h < HIDDEN; h += 32)
                p += W1[f * HIDDEN + h] * sW2[h];
            #pragma unroll
            for (int o = 16; o; o >>= 1)
                p += __shfl_down_sync(0xffffffffu, p, o);
            if (lane == 0) sw[f] = p;
        }
        __syncthreads();

        for (int i = b * TPB + t; i < N_NODES; i += Y_BLOCKS * TPB) {
            const float4* xr = reinterpret_cast<const float4*>(x + (size_t)i * NFEAT);
            float acc = 0.0f;
            #pragma unroll
            for (int j = 0; j < NFEAT / 4; j++) {
                float4 v = xr[j];
                acc += v.x * sw[4 * j + 0] + v.y * sw[4 * j + 1]
                     + v.z * sw[4 * j + 2] + v.w * sw[4 * j + 3];
            }
            g_y[i] = acc;
        }
    } else {
        const int4* cols = reinterpret_cast<const int4*>(ei + N_EDGES);
        const int   stride = DEG_BLOCKS * TPB;
        for (int tid = (b - Y_BLOCKS) * TPB + t; tid < EDGE_ITEMS; tid += stride) {
            int4 a = cols[2 * tid + 0];
            int4 c = cols[2 * tid + 1];
            atomicAdd(&g_deg[a.x], 1.0f);
            atomicAdd(&g_deg[a.y], 1.0f);
            atomicAdd(&g_deg[a.z], 1.0f);
            atomicAdd(&g_deg[a.w], 1.0f);
            atomicAdd(&g_deg[c.x], 1.0f);
            atomicAdd(&g_deg[c.y], 1.0f);
            atomicAdd(&g_deg[c.z], 1.0f);
            atomicAdd(&g_deg[c.w], 1.0f);
        }
    }
    grid_sync(0);

    // ===== Phase 2: dinv = rsqrt(deg+1); z = dinv*y; s seeded with z =====
    for (int tid = b * TPB + t; tid < NODE4; tid += GRID * TPB) {
        float4 d4 = reinterpret_cast<const float4*>(g_deg)[tid];
        float4 y4 = reinterpret_cast<const float4*>(g_y)[tid];
        float4 iv, z4;
        iv.x = rsqrtf(d4.x + 1.0f);  z4.x = iv.x * y4.x;
        iv.y = rsqrtf(d4.y + 1.0f);  z4.y = iv.y * y4.y;
        iv.z = rsqrtf(d4.z + 1.0f);  z4.z = iv.z * y4.z;
        iv.w = rsqrtf(d4.w + 1.0f);  z4.w = iv.w * y4.w;
        reinterpret_cast<float4*>(g_dinv)[tid] = iv;
        reinterpret_cast<float4*>(g_z)[tid]    = z4;
        reinterpret_cast<float4*>(g_s)[tid]    = z4;   // self-loop seed
    }
    grid_sync(1);

    // ===== Phase 3: edge scatter s[c] += z[r] (8 edges per item) =====
    {
        const int4* rows = reinterpret_cast<const int4*>(ei);
        const int4* cols = reinterpret_cast<const int4*>(ei + N_EDGES);
        for (int tid = b * TPB + t; tid < EDGE_ITEMS; tid += GRID * TPB) {
            int4 r0 = rows[2 * tid + 0];
            int4 r1 = rows[2 * tid + 1];
            int4 c0 = cols[2 * tid + 0];
            int4 c1 = cols[2 * tid + 1];
            float z0 = __ldg(&g_z[r0.x]);
            float z1 = __ldg(&g_z[r0.y]);
            float z2 = __ldg(&g_z[r0.z]);
            float z3 = __ldg(&g_z[r0.w]);
            float z4 = __ldg(&g_z[r1.x]);
            float z5 = __ldg(&g_z[r1.y]);
            float z6 = __ldg(&g_z[r1.z]);
            float z7 = __ldg(&g_z[r1.w]);
            atomicAdd(&g_s[c0.x], z0);
            atomicAdd(&g_s[c0.y], z1);
            atomicAdd(&g_s[c0.z], z2);
            atomicAdd(&g_s[c0.w], z3);
            atomicAdd(&g_s[c1.x], z4);
            atomicAdd(&g_s[c1.y], z5);
            atomicAdd(&g_s[c1.z], z6);
            atomicAdd(&g_s[c1.w], z7);
        }
    }
    grid_sync(2);

    // ===== Phase 4: out = dinv*s + cterm; reset g_deg for next call =====
    {
        const float cterm = g_cterm;
        const float4 zero4 = make_float4(0.f, 0.f, 0.f, 0.f);
        for (int tid = b * TPB + t; tid < NODE4; tid += GRID * TPB) {
            float4 iv = reinterpret_cast<const float4*>(g_dinv)[tid];
            float4 s4 = reinterpret_cast<const float4*>(g_s)[tid];
            float4 o4;
            o4.x = fmaf(iv.x, s4.x, cterm);
            o4.y = fmaf(iv.y, s4.y, cterm);
            o4.z = fmaf(iv.z, s4.z, cterm);
            o4.w = fmaf(iv.w, s4.w, cterm);
            reinterpret_cast<float4*>(out)[tid]   = o4;
            reinterpret_cast<float4*>(g_deg)[tid] = zero4;
        }
    }

    // ===== Exit protocol: block 0 resets barrier counters after ALL blocks
    //       have passed every barrier (no spinner can still read them). =====
    __syncthreads();
    if (t == 0) {
        __threadfence();
        atomicAdd(&g_bar[3], 1u);
        if (b == 0) {
            while (*(volatile unsigned*)&g_bar[3] < GRID) __nanosleep(64);
            g_bar[0] = 0; g_bar[1] = 0; g_bar[2] = 0; g_bar[3] = 0;
            __threadfence();
        }
    }
}

// ---------------------------------------------------------------------------
extern "C" void kernel_launch(void* const* d_in, const int* in_sizes, int n_in,
                              void* d_out, int out_size)
{
    const float* x    = (const float*)d_in[0];   // [N, 48]
    const int*   ei   = (const int*)  d_in[1];   // [2, E]
    const float* W1   = (const float*)d_in[2];   // [48, 256]
    const float* bias = (const float*)d_in[3];   // [1]
    const float* W2   = (const float*)d_in[4];   // [256, 1]
    const float* b2   = (const float*)d_in[5];   // [1]
    float* out = (float*)d_out;                  // [N, 1]

    k_fused<<<GRID, TPB>>>(x, ei, W1, bias, W2, b2, out);
}

// round 9
// speedup vs baseline: 1.3374x; 1.3374x over previous
#include <cuda_runtime.h>

#define N_NODES   100000
#define N_EDGES   1600000
#define NFEAT     48
#define HIDDEN    256
#define TPB       256
#define EPT       8                                    // edges per thread
#define EDGE_ITEMS  (N_EDGES / EPT)                    // 200000
#define EDGE_BLOCKS ((EDGE_ITEMS + TPB - 1) / TPB)     // 782
#define NODE_BLOCKS ((N_NODES + TPB - 1) / TPB)        // 391

// Device scratch. Zero-initialized at module load; k_final restores g_deg and
// g_s to all-zeros on EVERY call => identical starting state each call.
__device__ float g_deg[N_NODES];   // per-destination edge count
__device__ float g_y[N_NODES];     // x @ (W1@W2)
__device__ float g_z[N_NODES];     // rsqrt(deg+1) * y
__device__ float g_s[N_NODES];     // sum_{r->c} z[r]  (self-loop added in k_final)

// ---------------------------------------------------------------------------
// K1: blocks [0, EDGE_BLOCKS): degree histogram (8 edges/thread, RED only).
//     blocks [EDGE_BLOCKS, +NODE_BLOCKS): y = x . (W1@W2), weight fold done
//     redundantly per block (L2-hit W1 reads). Disjoint resources => overlap.
// ---------------------------------------------------------------------------
__global__ void __launch_bounds__(TPB) k_deg_y(const int*   __restrict__ ei,
                                               const float* __restrict__ x,
                                               const float* __restrict__ W1,
                                               const float* __restrict__ W2)
{
    if (threadIdx.x == 0) cudaTriggerProgrammaticLaunchCompletion();

    if (blockIdx.x < EDGE_BLOCKS) {
        int tid = blockIdx.x * TPB + threadIdx.x;
        if (tid >= EDGE_ITEMS) return;
        const int4* cols = reinterpret_cast<const int4*>(ei + N_EDGES);
        int4 a = cols[2 * tid + 0];
        int4 c = cols[2 * tid + 1];
        atomicAdd(&g_deg[a.x], 1.0f);
        atomicAdd(&g_deg[a.y], 1.0f);
        atomicAdd(&g_deg[a.z], 1.0f);
        atomicAdd(&g_deg[a.w], 1.0f);
        atomicAdd(&g_deg[c.x], 1.0f);
        atomicAdd(&g_deg[c.y], 1.0f);
        atomicAdd(&g_deg[c.z], 1.0f);
        atomicAdd(&g_deg[c.w], 1.0f);
        return;
    }

    // ---- node-dot blocks ----
    __shared__ float sW2[HIDDEN];
    __shared__ float sw[NFEAT];
    int t = threadIdx.x;
    sW2[t] = W2[t];
    __syncthreads();

    int warp = t >> 5, lane = t & 31;
    for (int f = warp; f < NFEAT; f += 8) {
        float p = 0.0f;
        #pragma unroll
        for (int h = lane; h < HIDDEN; h += 32)
            p += W1[f * HIDDEN + h] * sW2[h];
        #pragma unroll
        for (int o = 16; o; o >>= 1)
            p += __shfl_down_sync(0xffffffffu, p, o);
        if (lane == 0) sw[f] = p;
    }
    __syncthreads();

    int i = (blockIdx.x - EDGE_BLOCKS) * TPB + t;
    if (i >= N_NODES) return;
    const float4* xr = reinterpret_cast<const float4*>(x + (size_t)i * NFEAT);
    float acc = 0.0f;
    #pragma unroll
    for (int j = 0; j < NFEAT / 4; j++) {
        float4 v = xr[j];
        acc += v.x * sw[4 * j + 0] + v.y * sw[4 * j + 1]
             + v.z * sw[4 * j + 2] + v.w * sw[4 * j + 3];
    }
    g_y[i] = acc;
}

// ---------------------------------------------------------------------------
// K2 (PDL): z = rsqrt(deg+1) * y
// ---------------------------------------------------------------------------
__global__ void __launch_bounds__(TPB) k_z()
{
    if (threadIdx.x == 0) cudaTriggerProgrammaticLaunchCompletion();
    cudaGridDependencySynchronize();
    int i = blockIdx.x * TPB + threadIdx.x;
    if (i >= N_NODES) return;
    g_z[i] = rsqrtf(g_deg[i] + 1.0f) * g_y[i];
}

// ---------------------------------------------------------------------------
// K3 (PDL): prefetch edge indices (independent of predecessors), then sync,
//           then scatter s[c] += z[r]  (8 edges/thread, g_s pre-zeroed).
// ---------------------------------------------------------------------------
__global__ void __launch_bounds__(TPB) k_edges(const int* __restrict__ ei)
{
    if (threadIdx.x == 0) cudaTriggerProgrammaticLaunchCompletion();
    int tid = blockIdx.x * TPB + threadIdx.x;
    bool active = (tid < EDGE_ITEMS);
    int4 r0, r1, c0, c1;
    if (active) {
        const int4* rows = reinterpret_cast<const int4*>(ei);
        const int4* cols = reinterpret_cast<const int4*>(ei + N_EDGES);
        r0 = rows[2 * tid + 0];
        r1 = rows[2 * tid + 1];
        c0 = cols[2 * tid + 0];
        c1 = cols[2 * tid + 1];
    }
    cudaGridDependencySynchronize();
    if (!active) return;

    float z0 = __ldg(&g_z[r0.x]);
    float z1 = __ldg(&g_z[r0.y]);
    float z2 = __ldg(&g_z[r0.z]);
    float z3 = __ldg(&g_z[r0.w]);
    float z4 = __ldg(&g_z[r1.x]);
    float z5 = __ldg(&g_z[r1.y]);
    float z6 = __ldg(&g_z[r1.z]);
    float z7 = __ldg(&g_z[r1.w]);

    atomicAdd(&g_s[c0.x], z0);
    atomicAdd(&g_s[c0.y], z1);
    atomicAdd(&g_s[c0.z], z2);
    atomicAdd(&g_s[c0.w], z3);
    atomicAdd(&g_s[c1.x], z4);
    atomicAdd(&g_s[c1.y], z5);
    atomicAdd(&g_s[c1.z], z6);
    atomicAdd(&g_s[c1.w], z7);
}

// ---------------------------------------------------------------------------
// K4 (PDL): cterm reduction pre-sync, then out = rsqrt(deg+1)*(s+z) + cterm;
//           reset g_deg and g_s for the next call (state invariant).
// ---------------------------------------------------------------------------
__global__ void __launch_bounds__(TPB) k_final(float*       __restrict__ out,
                                               const float* __restrict__ bias,
                                               const float* __restrict__ W2,
                                               const float* __restrict__ b2)
{
    __shared__ float sred[TPB];
    int t = threadIdx.x;
    sred[t] = W2[t];                      // inputs only: safe pre-sync
    float b0 = bias[0], b20 = b2[0];
    __syncthreads();
    for (int s = TPB / 2; s > 0; s >>= 1) {
        if (t < s) sred[t] += sred[t + s];
        __syncthreads();
    }
    float cterm = b0 * sred[0] + b20;

    cudaGridDependencySynchronize();

    int i = blockIdx.x * TPB + t;
    if (i >= N_NODES) return;
    float dinv = rsqrtf(g_deg[i] + 1.0f);
    out[i] = dinv * (g_s[i] + g_z[i]) + cterm;   // self-loop z added here
    g_deg[i] = 0.0f;
    g_s[i]   = 0.0f;
}

// ---------------------------------------------------------------------------
extern "C" void kernel_launch(void* const* d_in, const int* in_sizes, int n_in,
                              void* d_out, int out_size)
{
    const float* x    = (const float*)d_in[0];   // [N, 48]
    const int*   ei   = (const int*)  d_in[1];   // [2, E]
    const float* W1   = (const float*)d_in[2];   // [48, 256]
    const float* bias = (const float*)d_in[3];   // [1]
    const float* W2   = (const float*)d_in[4];   // [256, 1]
    const float* b2   = (const float*)d_in[5];   // [1]
    float* out = (float*)d_out;                  // [N, 1]

    k_deg_y<<<EDGE_BLOCKS + NODE_BLOCKS, TPB>>>(ei, x, W1, W2);

    cudaLaunchAttribute at;
    at.id = cudaLaunchAttributeProgrammaticStreamSerialization;
    at.val.programmaticStreamSerializationAllowed = 1;

    cudaLaunchConfig_t cfg = {};
    cfg.blockDim = dim3(TPB, 1, 1);
    cfg.attrs    = &at;
    cfg.numAttrs = 1;
    cfg.stream   = (cudaStream_t)0;

    cfg.gridDim = dim3(NODE_BLOCKS, 1, 1);
    cudaLaunchKernelEx(&cfg, k_z);

    cfg.gridDim = dim3(EDGE_BLOCKS, 1, 1);
    cudaLaunchKernelEx(&cfg, k_edges, ei);

    cfg.gridDim = dim3(NODE_BLOCKS, 1, 1);
    cudaLaunchKernelEx(&cfg, k_final, out, bias, W2, b2);
}